// round 2
// baseline (speedup 1.0000x reference)
#include <cuda_runtime.h>
#include <math.h>

// Problem constants (fixed shapes per setup_inputs)
#define BSZ   1024
#define MOL   64
#define HID   512
#define NH    8
#define HD    64
#define NRBF  32
#define NPTS  (BSZ*MOL)          // 65536
#define QKVW  (3*HID)            // 1536

// Scratch (allocation-free rule: __device__ globals)
__device__ float g_qkv[(size_t)NPTS * QKVW];          // 384 MB
__device__ float g_bias[(size_t)BSZ * NH * MOL * MOL];// 128 MB
__device__ float g_agg[(size_t)NPTS * HID];           // 128 MB
__device__ float g_y[(size_t)NPTS * HID];             // 128 MB

// ---------------------------------------------------------------------------
// Tiled SGEMM: C[M,N] = A[M,K] @ B[K,N] + bias[N] (+ resid[M,N])
// BM=BN=128, BK=16, 256 threads, 8x8 per-thread tile.
// Register-prefetch pipeline: next tile's gmem loads issued before compute.
// ---------------------------------------------------------------------------
template<bool RESID>
__global__ __launch_bounds__(256, 2)
void sgemm128(int M, int N, int K,
              const float* __restrict__ A,
              const float* __restrict__ B,
              const float* __restrict__ bias,
              const float* __restrict__ resid,
              float* __restrict__ C)
{
    constexpr int BM = 128, BN = 128, BK = 16, TM = 8, TN = 8;
    __shared__ float As[BK][BM + 4];   // transposed A tile (pad keeps 16B align)
    __shared__ float Bs[BK][BN];

    const int tid  = threadIdx.x;
    const int tcol = tid % (BN / TN);  // 0..15
    const int trow = tid / (BN / TN);  // 0..15
    const int rowBase = blockIdx.y * BM;
    const int colBase = blockIdx.x * BN;

    const float* Ap = A + (size_t)rowBase * K;
    const float* Bp = B + colBase;

    const int aRow = tid >> 2;         // 0..63
    const int aCol = (tid & 3) << 2;   // 0,4,8,12
    const int bRow = tid >> 5;         // 0..7
    const int bCol = (tid & 31) << 2;  // 0..124

    float acc[TM][TN];
#pragma unroll
    for (int i = 0; i < TM; i++)
#pragma unroll
        for (int j = 0; j < TN; j++) acc[i][j] = 0.f;

    // Prologue: load tile 0 directly into smem
    {
#pragma unroll
        for (int off = 0; off < BM; off += 64) {
            float4 v = *reinterpret_cast<const float4*>(
                Ap + (size_t)(aRow + off) * K + aCol);
            As[aCol + 0][aRow + off] = v.x;
            As[aCol + 1][aRow + off] = v.y;
            As[aCol + 2][aRow + off] = v.z;
            As[aCol + 3][aRow + off] = v.w;
        }
#pragma unroll
        for (int off = 0; off < BK; off += 8) {
            *reinterpret_cast<float4*>(&Bs[bRow + off][bCol]) =
                *reinterpret_cast<const float4*>(
                    Bp + (size_t)(bRow + off) * N + bCol);
        }
    }
    __syncthreads();

    float4 pa[2], pb[2];
    for (int k0 = 0; k0 < K; k0 += BK) {
        const int kn = k0 + BK;
        const bool more = (kn < K);
        // Prefetch next tile gmem -> regs (latency hidden behind compute)
        if (more) {
#pragma unroll
            for (int t = 0; t < 2; t++)
                pa[t] = *reinterpret_cast<const float4*>(
                    Ap + (size_t)(aRow + t * 64) * K + kn + aCol);
#pragma unroll
            for (int t = 0; t < 2; t++)
                pb[t] = *reinterpret_cast<const float4*>(
                    Bp + (size_t)(kn + bRow + t * 8) * N + bCol);
        }

#pragma unroll
        for (int kk = 0; kk < BK; kk++) {
            float ra[TM], rb[TN];
#pragma unroll
            for (int i = 0; i < TM; i++) ra[i] = As[kk][trow * TM + i];
#pragma unroll
            for (int j = 0; j < TN; j++) rb[j] = Bs[kk][tcol * TN + j];
#pragma unroll
            for (int i = 0; i < TM; i++)
#pragma unroll
                for (int j = 0; j < TN; j++)
                    acc[i][j] = fmaf(ra[i], rb[j], acc[i][j]);
        }
        __syncthreads();

        if (more) {
#pragma unroll
            for (int t = 0; t < 2; t++) {
                As[aCol + 0][aRow + t * 64] = pa[t].x;
                As[aCol + 1][aRow + t * 64] = pa[t].y;
                As[aCol + 2][aRow + t * 64] = pa[t].z;
                As[aCol + 3][aRow + t * 64] = pa[t].w;
            }
#pragma unroll
            for (int t = 0; t < 2; t++)
                *reinterpret_cast<float4*>(&Bs[bRow + t * 8][bCol]) = pb[t];
            __syncthreads();
        }
    }

#pragma unroll
    for (int i = 0; i < TM; i++) {
        const int gRow = rowBase + trow * TM + i;
#pragma unroll
        for (int j = 0; j < TN; j += 4) {
            const int gCol = colBase + tcol * TN + j;
            float4 o;
            o.x = acc[i][j + 0] + bias[gCol + 0];
            o.y = acc[i][j + 1] + bias[gCol + 1];
            o.z = acc[i][j + 2] + bias[gCol + 2];
            o.w = acc[i][j + 3] + bias[gCol + 3];
            if (RESID) {
                float4 r = *reinterpret_cast<const float4*>(
                    resid + (size_t)gRow * N + gCol);
                o.x += r.x; o.y += r.y; o.z += r.z; o.w += r.w;
            }
            *reinterpret_cast<float4*>(C + (size_t)gRow * N + gCol) = o;
        }
    }
}

// ---------------------------------------------------------------------------
// RBF bias: bias[b,h,i,j] = b_rbf[h] + sum_r exp(-(d_ij - c_r)^2 * 16) * w_rbf[r,h]
// One block per molecule; exp computed once, shared across all 8 heads.
// ---------------------------------------------------------------------------
__global__ __launch_bounds__(256)
void bias_kernel(const float* __restrict__ pos,
                 const float* __restrict__ centers,
                 const float* __restrict__ w_rbf,
                 const float* __restrict__ b_rbf,
                 float* __restrict__ biasOut)
{
    __shared__ float px[MOL], py[MOL], pz[MOL];
    __shared__ float sc[NRBF];
    __shared__ float sw[NRBF][NH];
    __shared__ float sb[NH];

    const int b = blockIdx.x;
    const int tid = threadIdx.x;
    if (tid < MOL) {
        px[tid] = pos[(size_t)(b * MOL + tid) * 3 + 0];
        py[tid] = pos[(size_t)(b * MOL + tid) * 3 + 1];
        pz[tid] = pos[(size_t)(b * MOL + tid) * 3 + 2];
    }
    if (tid < NRBF) sc[tid] = centers[tid];
    if (tid < NRBF * NH) sw[tid / NH][tid % NH] = w_rbf[tid];
    if (tid < NH) sb[tid] = b_rbf[tid];
    __syncthreads();

    // inv_width = (NRBF/CUTOFF)^2 = (32/8)^2 = 16
    const float INVW = 16.0f;

    for (int p = tid; p < MOL * MOL; p += 256) {
        const int i = p >> 6, j = p & 63;
        float dx = px[i] - px[j], dy = py[i] - py[j], dz = pz[i] - pz[j];
        float d2 = dx * dx + dy * dy + dz * dz;
        float dist = sqrtf(fmaxf(d2, 1e-12f));
        float acc[NH];
#pragma unroll
        for (int h = 0; h < NH; h++) acc[h] = sb[h];
#pragma unroll
        for (int r = 0; r < NRBF; r++) {
            float t = dist - sc[r];
            float e = __expf(-t * t * INVW);
#pragma unroll
            for (int h = 0; h < NH; h++) acc[h] = fmaf(e, sw[r][h], acc[h]);
        }
        size_t base = (size_t)b * NH * MOL * MOL + (size_t)i * MOL + j;
#pragma unroll
        for (int h = 0; h < NH; h++)
            biasOut[base + (size_t)h * MOL * MOL] = acc[h];
    }
}

// ---------------------------------------------------------------------------
// Attention: one block per (head, molecule). q,kT,v tiles in 48KB smem.
// Warp w owns rows 8w..8w+7; lane l owns cols {l, l+32}. kT XOR-swizzled.
// Score-phase p overwrites the q smem tile (disjoint rows per warp).
// ---------------------------------------------------------------------------
__global__ __launch_bounds__(256)
void attn_kernel(const float* __restrict__ qkv,
                 const float* __restrict__ biasIn,
                 float* __restrict__ agg)
{
    __shared__ float sq[MOL * HD];     // q tile, later reused for softmax p
    __shared__ float skT[HD * MOL];    // k transposed, XOR-swizzled
    __shared__ float sv[MOL * HD];     // v tile

    const int h = blockIdx.x;
    const int b = blockIdx.y;
    const int tid  = threadIdx.x;
    const int lane = tid & 31;
    const int warp = tid >> 5;         // 0..7

    // Vectorized global load; skT scatter with swizzle (i ^ (d&31))
    for (int e4 = tid; e4 < MOL * (HD / 4); e4 += 256) {
        const int i  = e4 >> 4;
        const int d4 = (e4 & 15) << 2;
        const size_t rowbase = (size_t)(b * MOL + i) * QKVW + h * HD + d4;
        float4 q = *reinterpret_cast<const float4*>(qkv + rowbase);
        float4 k = *reinterpret_cast<const float4*>(qkv + rowbase + HID);
        float4 v = *reinterpret_cast<const float4*>(qkv + rowbase + 2 * HID);
        *reinterpret_cast<float4*>(&sq[i * HD + d4]) = q;
        *reinterpret_cast<float4*>(&sv[i * HD + d4]) = v;
        skT[(d4 + 0) * MOL + (i ^ ((d4 + 0) & 31))] = k.x;
        skT[(d4 + 1) * MOL + (i ^ ((d4 + 1) & 31))] = k.y;
        skT[(d4 + 2) * MOL + (i ^ ((d4 + 2) & 31))] = k.z;
        skT[(d4 + 3) * MOL + (i ^ ((d4 + 3) & 31))] = k.w;
    }
    __syncthreads();

    const int i0 = warp * 8;
    float s[8][2];
#pragma unroll
    for (int r = 0; r < 8; r++) { s[r][0] = 0.f; s[r][1] = 0.f; }

    // scores: s[i][j] = sum_d q[i][d] * k[j][d]
#pragma unroll 4
    for (int d = 0; d < HD; d++) {
        const int sl = lane ^ (d & 31);
        const float k0 = skT[d * MOL + sl];
        const float k1 = skT[d * MOL + sl + 32];
#pragma unroll
        for (int r = 0; r < 8; r++) {
            const float qv = sq[(i0 + r) * HD + d];
            s[r][0] = fmaf(qv, k0, s[r][0]);
            s[r][1] = fmaf(qv, k1, s[r][1]);
        }
    }

    // softmax with RBF bias; write p into sq (own rows only)
    const float* bptr = biasIn + ((size_t)b * NH + h) * MOL * MOL;
#pragma unroll
    for (int r = 0; r < 8; r++) {
        const int i = i0 + r;
        float v0 = s[r][0] * 0.125f + bptr[i * MOL + lane];
        float v1 = s[r][1] * 0.125f + bptr[i * MOL + lane + 32];
        float m = fmaxf(v0, v1);
#pragma unroll
        for (int o = 16; o > 0; o >>= 1)
            m = fmaxf(m, __shfl_xor_sync(0xffffffffu, m, o));
        float e0 = __expf(v0 - m);
        float e1 = __expf(v1 - m);
        float sum = e0 + e1;
#pragma unroll
        for (int o = 16; o > 0; o >>= 1)
            sum += __shfl_xor_sync(0xffffffffu, sum, o);
        const float inv = 1.0f / sum;
        sq[i * HD + lane]      = e0 * inv;
        sq[i * HD + lane + 32] = e1 * inv;
    }
    __syncwarp();

    // aggregate: out[i][d] = sum_j p[i][j] * v[j][d]
    float o[8][2];
#pragma unroll
    for (int r = 0; r < 8; r++) { o[r][0] = 0.f; o[r][1] = 0.f; }
#pragma unroll 4
    for (int j = 0; j < MOL; j++) {
        const float v0 = sv[j * HD + lane];
        const float v1 = sv[j * HD + lane + 32];
#pragma unroll
        for (int r = 0; r < 8; r++) {
            const float p = sq[(i0 + r) * HD + j];
            o[r][0] = fmaf(p, v0, o[r][0]);
            o[r][1] = fmaf(p, v1, o[r][1]);
        }
    }
#pragma unroll
    for (int r = 0; r < 8; r++) {
        const int i = i0 + r;
        const size_t obase = (size_t)(b * MOL + i) * HID + h * HD;
        agg[obase + lane]      = o[r][0];
        agg[obase + lane + 32] = o[r][1];
    }
}

// ---------------------------------------------------------------------------
// LayerNorm: one warp per row of 512; y already contains residual.
// ---------------------------------------------------------------------------
__global__ __launch_bounds__(256)
void ln_kernel(const float* __restrict__ y,
               const float* __restrict__ gamma,
               const float* __restrict__ beta,
               float* __restrict__ out)
{
    const int row  = blockIdx.x * 8 + (threadIdx.x >> 5);
    const int lane = threadIdx.x & 31;
    const float4* y4 = reinterpret_cast<const float4*>(y + (size_t)row * HID);
    float4 v[4];
    float sum = 0.f, sq = 0.f;
#pragma unroll
    for (int c = 0; c < 4; c++) {
        v[c] = y4[c * 32 + lane];
        sum += v[c].x + v[c].y + v[c].z + v[c].w;
        sq  += v[c].x * v[c].x + v[c].y * v[c].y + v[c].z * v[c].z + v[c].w * v[c].w;
    }
#pragma unroll
    for (int o = 16; o > 0; o >>= 1) {
        sum += __shfl_xor_sync(0xffffffffu, sum, o);
        sq  += __shfl_xor_sync(0xffffffffu, sq, o);
    }
    const float mu   = sum * (1.0f / HID);
    const float var  = sq * (1.0f / HID) - mu * mu;
    const float rstd = rsqrtf(var + 1e-5f);

    float4* o4 = reinterpret_cast<float4*>(out + (size_t)row * HID);
    const float4* g4 = reinterpret_cast<const float4*>(gamma);
    const float4* b4 = reinterpret_cast<const float4*>(beta);
#pragma unroll
    for (int c = 0; c < 4; c++) {
        const float4 g  = g4[c * 32 + lane];
        const float4 bt = b4[c * 32 + lane];
        float4 r;
        r.x = (v[c].x - mu) * rstd * g.x + bt.x;
        r.y = (v[c].y - mu) * rstd * g.y + bt.y;
        r.z = (v[c].z - mu) * rstd * g.z + bt.z;
        r.w = (v[c].w - mu) * rstd * g.w + bt.w;
        o4[c * 32 + lane] = r;
    }
}

// ---------------------------------------------------------------------------
extern "C" void kernel_launch(void* const* d_in, const int* in_sizes, int n_in,
                              void* d_out, int out_size)
{
    const float* h_in   = (const float*)d_in[0];
    const float* pos    = (const float*)d_in[1];
    /* d_in[2] = batch (int32) unused: equal-size contiguous molecules */
    const float* centers= (const float*)d_in[3];
    const float* w_rbf  = (const float*)d_in[4];
    const float* b_rbf  = (const float*)d_in[5];
    const float* w_qkv  = (const float*)d_in[6];
    const float* b_qkv  = (const float*)d_in[7];
    const float* w_out  = (const float*)d_in[8];
    const float* b_out  = (const float*)d_in[9];
    const float* gamma  = (const float*)d_in[10];
    const float* beta   = (const float*)d_in[11];
    float* out = (float*)d_out;

    float *qkv, *biasb, *aggp, *yp;
    cudaGetSymbolAddress((void**)&qkv,   g_qkv);
    cudaGetSymbolAddress((void**)&biasb, g_bias);
    cudaGetSymbolAddress((void**)&aggp,  g_agg);
    cudaGetSymbolAddress((void**)&yp,    g_y);

    // 1) QKV projection: [65536,512] @ [512,1536]
    sgemm128<false><<<dim3(QKVW / 128, NPTS / 128), 256>>>(
        NPTS, QKVW, HID, h_in, w_qkv, b_qkv, nullptr, qkv);

    // 2) RBF attention bias per molecule (independent of (1))
    bias_kernel<<<BSZ, 256>>>(pos, centers, w_rbf, b_rbf, biasb);

    // 3) Block-diagonal attention per (head, molecule)
    attn_kernel<<<dim3(NH, BSZ), 256>>>(qkv, biasb, aggp);

    // 4) Output projection + bias + residual: [65536,512] @ [512,512] + h
    sgemm128<true><<<dim3(HID / 128, NPTS / 128), 256>>>(
        NPTS, HID, HID, aggp, w_out, b_out, h_in, yp);

    // 5) LayerNorm
    ln_kernel<<<NPTS / 8, 256>>>(yp, gamma, beta, out);
}

// round 5
// speedup vs baseline: 2.0165x; 2.0165x over previous
#include <cuda_runtime.h>
#include <cuda_bf16.h>
#include <math.h>
#include <cstdint>

// Problem constants (fixed shapes per setup_inputs)
#define BSZ   1024
#define MOL   64
#define HID   512
#define NH    8
#define HD    64
#define NRBF  32
#define NPTS  (BSZ*MOL)          // 65536
#define QKVW  (3*HID)            // 1536

// ---------------------------------------------------------------------------
// Scratch (allocation-free rule: __device__ globals)
// ---------------------------------------------------------------------------
__device__ float g_qkv[(size_t)NPTS * QKVW];            // 384 MB fp32
__device__ float g_bias[(size_t)BSZ * NH * MOL * MOL];  // 128 MB
__device__ float g_y[(size_t)NPTS * HID];               // 128 MB
__device__ __nv_bfloat16 g_ahi[(size_t)NPTS * HID];     // h split hi
__device__ __nv_bfloat16 g_alo[(size_t)NPTS * HID];     // h split lo
__device__ __nv_bfloat16 g_gghi[(size_t)NPTS * HID];    // agg split hi
__device__ __nv_bfloat16 g_gglo[(size_t)NPTS * HID];    // agg split lo
__device__ __nv_bfloat16 g_wqhi[(size_t)QKVW * HID];    // w_qkv^T hi [1536,512]
__device__ __nv_bfloat16 g_wqlo[(size_t)QKVW * HID];
__device__ __nv_bfloat16 g_wohi[(size_t)HID * HID];     // w_out^T hi [512,512]
__device__ __nv_bfloat16 g_wolo[(size_t)HID * HID];

// ---------------------------------------------------------------------------
// Baseline-PTX tensor helpers (compute_100-safe: mma.sync / ldmatrix / cp.async)
// ---------------------------------------------------------------------------
__device__ __forceinline__ uint32_t smem_to_u32(const void* p) {
    uint32_t a;
    asm("{ .reg .u64 t; cvta.to.shared.u64 t, %1; cvt.u32.u64 %0, t; }" : "=r"(a) : "l"(p));
    return a;
}
__device__ __forceinline__ void cp16(uint32_t dst, const void* src) {
    asm volatile("cp.async.cg.shared.global [%0], [%1], 16;" :: "r"(dst), "l"(src));
}
__device__ __forceinline__ void ldsm_x4(uint32_t* r, uint32_t addr) {
    asm volatile("ldmatrix.sync.aligned.m8n8.x4.shared.b16 {%0,%1,%2,%3}, [%4];"
                 : "=r"(r[0]), "=r"(r[1]), "=r"(r[2]), "=r"(r[3]) : "r"(addr));
}
__device__ __forceinline__ void ldsm_x2(uint32_t* r, uint32_t addr) {
    asm volatile("ldmatrix.sync.aligned.m8n8.x2.shared.b16 {%0,%1}, [%2];"
                 : "=r"(r[0]), "=r"(r[1]) : "r"(addr));
}
__device__ __forceinline__ void mma16816(float* c, const uint32_t* a, const uint32_t* b) {
    asm volatile("mma.sync.aligned.m16n8k16.row.col.f32.bf16.bf16.f32 "
                 "{%0,%1,%2,%3}, {%4,%5,%6,%7}, {%8,%9}, {%0,%1,%2,%3};"
                 : "+f"(c[0]), "+f"(c[1]), "+f"(c[2]), "+f"(c[3])
                 : "r"(a[0]), "r"(a[1]), "r"(a[2]), "r"(a[3]), "r"(b[0]), "r"(b[1]));
}
#define SWZ128(o) ((o) ^ (((o) >> 3) & 0x70))

// ---------------------------------------------------------------------------
// bf16x3 split GEMM on mma.sync: C[M,N] = (Ahi+Alo)[M,K=512] @ (Bhi+Blo)[N,K]^T
//                                        + bias (+resid)
// CTA tile 128x128, BK=64, 8 warps (2x4), warp tile 64x32.
// Smem: 4 tiles x 16KB, double-buffered (128KB). cp.async pipeline.
// ---------------------------------------------------------------------------
template<bool RESID>
__global__ __launch_bounds__(256)
void mmagemm(const __nv_bfloat16* __restrict__ Ahi, const __nv_bfloat16* __restrict__ Alo,
             const __nv_bfloat16* __restrict__ Bhi, const __nv_bfloat16* __restrict__ Blo,
             const float* __restrict__ bias, const float* __restrict__ resid,
             float* __restrict__ C, int N)
{
    constexpr int K = 512, NCH = 8;          // 8 chunks of BK=64
    constexpr uint32_t BUF = 65536;          // 4 x 16KB sub-tiles per buffer
    extern __shared__ char smem[];
    const uint32_t sbase = smem_to_u32(smem);
    const int tid  = threadIdx.x;
    const int lane = tid & 31;
    const int wid  = tid >> 5;
    const int mW   = wid >> 2;               // 0..1  -> m offset 64*mW
    const int nW   = wid & 3;                // 0..3  -> n offset 32*nW
    const int mBase = blockIdx.y * 128;
    const int nBase = blockIdx.x * 128;

    float acc[4][4][4];
#pragma unroll
    for (int mi = 0; mi < 4; mi++)
#pragma unroll
        for (int ni = 0; ni < 4; ni++)
#pragma unroll
            for (int e = 0; e < 4; e++) acc[mi][ni][e] = 0.f;

    // ---- async tile loader: chunk ch -> buffer ch&1 ----
    const int segRow = 0;  (void)segRow;
#define LOAD_CHUNK(ch) do {                                                     \
        const int _kB = (ch) * 64;                                              \
        const uint32_t _buf = sbase + ((ch) & 1) * BUF;                         \
        _Pragma("unroll")                                                       \
        for (int _i = 0; _i < 4; _i++) {                                        \
            const int _seg = _i * 256 + tid;                                    \
            const int _row = _seg >> 3, _c16 = _seg & 7;                        \
            const uint32_t _so = SWZ128((uint32_t)(_row * 128 + _c16 * 16));    \
            const size_t _ao = (size_t)(mBase + _row) * K + _kB + _c16 * 8;     \
            const size_t _bo = (size_t)(nBase + _row) * K + _kB + _c16 * 8;     \
            cp16(_buf + _so,         Ahi + _ao);                                \
            cp16(_buf + 16384 + _so, Alo + _ao);                                \
            cp16(_buf + 32768 + _so, Bhi + _bo);                                \
            cp16(_buf + 49152 + _so, Blo + _bo);                                \
        }                                                                       \
        asm volatile("cp.async.commit_group;");                                 \
    } while (0)

    LOAD_CHUNK(0);

    for (int ch = 0; ch < NCH; ch++) {
        if (ch + 1 < NCH) {
            LOAD_CHUNK(ch + 1);
            asm volatile("cp.async.wait_group 1;");
        } else {
            asm volatile("cp.async.wait_group 0;");
        }
        __syncthreads();

        const uint32_t buf = sbase + (ch & 1) * BUF;
#pragma unroll
        for (int ks = 0; ks < 4; ks++) {
            uint32_t ah[4][4], al[4][4], bh[4][2], bl[4][2];
            const uint32_t aRow = (uint32_t)(mW * 64 + (lane & 15));
            const uint32_t aCol = (uint32_t)(ks * 16 + ((lane >> 4) << 3)) * 2;
#pragma unroll
            for (int mi = 0; mi < 4; mi++) {
                const uint32_t o = SWZ128((aRow + (uint32_t)mi * 16) * 128 + aCol);
                ldsm_x4(ah[mi], buf + o);
                ldsm_x4(al[mi], buf + 16384 + o);
            }
            const uint32_t bRow = (uint32_t)(nW * 32 + (lane & 7));
            const uint32_t bCol = (uint32_t)(ks * 16 + ((lane >> 3) & 1) * 8) * 2;
#pragma unroll
            for (int ni = 0; ni < 4; ni++) {
                const uint32_t o = SWZ128((bRow + (uint32_t)ni * 8) * 128 + bCol);
                ldsm_x2(bh[ni], buf + 32768 + o);
                ldsm_x2(bl[ni], buf + 49152 + o);
            }
#pragma unroll
            for (int mi = 0; mi < 4; mi++)
#pragma unroll
                for (int ni = 0; ni < 4; ni++) {
                    mma16816(acc[mi][ni], ah[mi], bh[ni]);   // hi*hi
                    mma16816(acc[mi][ni], ah[mi], bl[ni]);   // hi*lo
                    mma16816(acc[mi][ni], al[mi], bh[ni]);   // lo*hi
                }
        }
        __syncthreads();
    }
#undef LOAD_CHUNK

    // ---- epilogue: c-frag (d0,d1)->(r, c..c+1), (d2,d3)->(r+8, c..c+1) ----
    const int r0 = mBase + mW * 64 + (lane >> 2);
    const int c0 = nBase + nW * 32 + (lane & 3) * 2;
#pragma unroll
    for (int mi = 0; mi < 4; mi++) {
#pragma unroll
        for (int ni = 0; ni < 4; ni++) {
            const int row = r0 + mi * 16;
            const int col = c0 + ni * 8;
            const float2 bb = *(const float2*)(bias + col);
            float2 o0, o1;
            o0.x = acc[mi][ni][0] + bb.x;  o0.y = acc[mi][ni][1] + bb.y;
            o1.x = acc[mi][ni][2] + bb.x;  o1.y = acc[mi][ni][3] + bb.y;
            if (RESID) {
                const float2 ra = *(const float2*)(resid + (size_t)row * N + col);
                const float2 rb = *(const float2*)(resid + (size_t)(row + 8) * N + col);
                o0.x += ra.x; o0.y += ra.y; o1.x += rb.x; o1.y += rb.y;
            }
            *(float2*)(C + (size_t)row * N + col)       = o0;
            *(float2*)(C + (size_t)(row + 8) * N + col) = o1;
        }
    }
}

// ---------------------------------------------------------------------------
// Elementwise split: x (fp32) -> hi/lo bf16 pair
// ---------------------------------------------------------------------------
__global__ __launch_bounds__(256)
void split_act(const float* __restrict__ x,
               __nv_bfloat16* __restrict__ hi, __nv_bfloat16* __restrict__ lo, int n4)
{
    const float4* x4 = (const float4*)x;
    __nv_bfloat162* h2 = (__nv_bfloat162*)hi;
    __nv_bfloat162* l2 = (__nv_bfloat162*)lo;
    for (int i = blockIdx.x * 256 + threadIdx.x; i < n4; i += gridDim.x * 256) {
        float4 v = x4[i];
        __nv_bfloat16 h0 = __float2bfloat16(v.x), h1 = __float2bfloat16(v.y);
        __nv_bfloat16 h2v = __float2bfloat16(v.z), h3 = __float2bfloat16(v.w);
        __nv_bfloat16 l0 = __float2bfloat16(v.x - __bfloat162float(h0));
        __nv_bfloat16 l1 = __float2bfloat16(v.y - __bfloat162float(h1));
        __nv_bfloat16 l2v = __float2bfloat16(v.z - __bfloat162float(h2v));
        __nv_bfloat16 l3 = __float2bfloat16(v.w - __bfloat162float(h3));
        h2[i * 2]     = __nv_bfloat162(h0, h1);
        h2[i * 2 + 1] = __nv_bfloat162(h2v, h3);
        l2[i * 2]     = __nv_bfloat162(l0, l1);
        l2[i * 2 + 1] = __nv_bfloat162(l2v, l3);
    }
}

// ---------------------------------------------------------------------------
// Transpose + split: W[Kd, Nd] fp32 -> out[n*Kd + k] hi/lo bf16
// ---------------------------------------------------------------------------
__global__ __launch_bounds__(256)
void transpose_split(const float* __restrict__ W,
                     __nv_bfloat16* __restrict__ hi, __nv_bfloat16* __restrict__ lo,
                     int Kd, int Nd)
{
    __shared__ float t[32][33];
    const int kb = blockIdx.x * 32, nb = blockIdx.y * 32;
    const int tx = threadIdx.x & 31, ty = threadIdx.x >> 5;  // (32,8)
#pragma unroll
    for (int j = 0; j < 32; j += 8)
        t[ty + j][tx] = W[(size_t)(kb + ty + j) * Nd + nb + tx];
    __syncthreads();
#pragma unroll
    for (int j = 0; j < 32; j += 8) {
        float v = t[tx][ty + j];
        __nv_bfloat16 h = __float2bfloat16(v);
        __nv_bfloat16 l = __float2bfloat16(v - __bfloat162float(h));
        hi[(size_t)(nb + ty + j) * Kd + kb + tx] = h;
        lo[(size_t)(nb + ty + j) * Kd + kb + tx] = l;
    }
}

// ---------------------------------------------------------------------------
// RBF bias
// ---------------------------------------------------------------------------
__global__ __launch_bounds__(256)
void bias_kernel(const float* __restrict__ pos,
                 const float* __restrict__ centers,
                 const float* __restrict__ w_rbf,
                 const float* __restrict__ b_rbf,
                 float* __restrict__ biasOut)
{
    __shared__ float px[MOL], py[MOL], pz[MOL];
    __shared__ float sc[NRBF];
    __shared__ float sw[NRBF][NH];
    __shared__ float sb[NH];

    const int b = blockIdx.x;
    const int tid = threadIdx.x;
    if (tid < MOL) {
        px[tid] = pos[(size_t)(b * MOL + tid) * 3 + 0];
        py[tid] = pos[(size_t)(b * MOL + tid) * 3 + 1];
        pz[tid] = pos[(size_t)(b * MOL + tid) * 3 + 2];
    }
    if (tid < NRBF) sc[tid] = centers[tid];
    if (tid < NRBF * NH) sw[tid / NH][tid % NH] = w_rbf[tid];
    if (tid < NH) sb[tid] = b_rbf[tid];
    __syncthreads();

    const float INVW = 16.0f;   // (NRBF/CUTOFF)^2

    for (int p = tid; p < MOL * MOL; p += 256) {
        const int i = p >> 6, j = p & 63;
        float dx = px[i] - px[j], dy = py[i] - py[j], dz = pz[i] - pz[j];
        float d2 = dx * dx + dy * dy + dz * dz;
        float dist = sqrtf(fmaxf(d2, 1e-12f));
        float acc[NH];
#pragma unroll
        for (int h = 0; h < NH; h++) acc[h] = sb[h];
#pragma unroll
        for (int rr = 0; rr < NRBF; rr++) {
            float tt = dist - sc[rr];
            float e = __expf(-tt * tt * INVW);
#pragma unroll
            for (int h = 0; h < NH; h++) acc[h] = fmaf(e, sw[rr][h], acc[h]);
        }
        size_t base = (size_t)b * NH * MOL * MOL + (size_t)i * MOL + j;
#pragma unroll
        for (int h = 0; h < NH; h++)
            biasOut[base + (size_t)h * MOL * MOL] = acc[h];
    }
}

// ---------------------------------------------------------------------------
// Attention (fp32 math; outputs hi/lo bf16 split for tensor-core out-proj)
// ---------------------------------------------------------------------------
__global__ __launch_bounds__(256)
void attn_kernel(const float* __restrict__ qkv,
                 const float* __restrict__ biasIn,
                 __nv_bfloat16* __restrict__ aggHi,
                 __nv_bfloat16* __restrict__ aggLo)
{
    __shared__ float sq[MOL * HD];
    __shared__ float skT[HD * MOL];
    __shared__ float sv[MOL * HD];

    const int h = blockIdx.x;
    const int b = blockIdx.y;
    const int tid  = threadIdx.x;
    const int lane = tid & 31;
    const int warp = tid >> 5;

    for (int e4 = tid; e4 < MOL * (HD / 4); e4 += 256) {
        const int i  = e4 >> 4;
        const int d4 = (e4 & 15) << 2;
        const size_t rowbase = (size_t)(b * MOL + i) * QKVW + h * HD + d4;
        float4 q = *reinterpret_cast<const float4*>(qkv + rowbase);
        float4 k = *reinterpret_cast<const float4*>(qkv + rowbase + HID);
        float4 v = *reinterpret_cast<const float4*>(qkv + rowbase + 2 * HID);
        *reinterpret_cast<float4*>(&sq[i * HD + d4]) = q;
        *reinterpret_cast<float4*>(&sv[i * HD + d4]) = v;
        skT[(d4 + 0) * MOL + (i ^ ((d4 + 0) & 31))] = k.x;
        skT[(d4 + 1) * MOL + (i ^ ((d4 + 1) & 31))] = k.y;
        skT[(d4 + 2) * MOL + (i ^ ((d4 + 2) & 31))] = k.z;
        skT[(d4 + 3) * MOL + (i ^ ((d4 + 3) & 31))] = k.w;
    }
    __syncthreads();

    const int i0 = warp * 8;
    float s[8][2];
#pragma unroll
    for (int r = 0; r < 8; r++) { s[r][0] = 0.f; s[r][1] = 0.f; }

#pragma unroll 4
    for (int d = 0; d < HD; d++) {
        const int sl = lane ^ (d & 31);
        const float k0 = skT[d * MOL + sl];
        const float k1 = skT[d * MOL + sl + 32];
#pragma unroll
        for (int r = 0; r < 8; r++) {
            const float qv = sq[(i0 + r) * HD + d];
            s[r][0] = fmaf(qv, k0, s[r][0]);
            s[r][1] = fmaf(qv, k1, s[r][1]);
        }
    }

    const float* bptr = biasIn + ((size_t)b * NH + h) * MOL * MOL;
#pragma unroll
    for (int r = 0; r < 8; r++) {
        const int i = i0 + r;
        float v0 = s[r][0] * 0.125f + bptr[i * MOL + lane];
        float v1 = s[r][1] * 0.125f + bptr[i * MOL + lane + 32];
        float m = fmaxf(v0, v1);
#pragma unroll
        for (int o = 16; o > 0; o >>= 1)
            m = fmaxf(m, __shfl_xor_sync(0xffffffffu, m, o));
        float e0 = __expf(v0 - m);
        float e1 = __expf(v1 - m);
        float sum = e0 + e1;
#pragma unroll
        for (int o = 16; o > 0; o >>= 1)
            sum += __shfl_xor_sync(0xffffffffu, sum, o);
        const float inv = 1.0f / sum;
        sq[i * HD + lane]      = e0 * inv;
        sq[i * HD + lane + 32] = e1 * inv;
    }
    __syncwarp();

    float o[8][2];
#pragma unroll
    for (int r = 0; r < 8; r++) { o[r][0] = 0.f; o[r][1] = 0.f; }
#pragma unroll 4
    for (int j = 0; j < MOL; j++) {
        const float v0 = sv[j * HD + lane];
        const float v1 = sv[j * HD + lane + 32];
#pragma unroll
        for (int r = 0; r < 8; r++) {
            const float p = sq[(i0 + r) * HD + j];
            o[r][0] = fmaf(p, v0, o[r][0]);
            o[r][1] = fmaf(p, v1, o[r][1]);
        }
    }
#pragma unroll
    for (int r = 0; r < 8; r++) {
        const int i = i0 + r;
        const size_t obase = (size_t)(b * MOL + i) * HID + h * HD;
        float a0 = o[r][0], a1 = o[r][1];
        __nv_bfloat16 h0 = __float2bfloat16(a0);
        __nv_bfloat16 h1 = __float2bfloat16(a1);
        aggHi[obase + lane]      = h0;
        aggHi[obase + lane + 32] = h1;
        aggLo[obase + lane]      = __float2bfloat16(a0 - __bfloat162float(h0));
        aggLo[obase + lane + 32] = __float2bfloat16(a1 - __bfloat162float(h1));
    }
}

// ---------------------------------------------------------------------------
// LayerNorm
// ---------------------------------------------------------------------------
__global__ __launch_bounds__(256)
void ln_kernel(const float* __restrict__ y,
               const float* __restrict__ gamma,
               const float* __restrict__ beta,
               float* __restrict__ out)
{
    const int row  = blockIdx.x * 8 + (threadIdx.x >> 5);
    const int lane = threadIdx.x & 31;
    const float4* y4 = reinterpret_cast<const float4*>(y + (size_t)row * HID);
    float4 v[4];
    float sum = 0.f, sq = 0.f;
#pragma unroll
    for (int c = 0; c < 4; c++) {
        v[c] = y4[c * 32 + lane];
        sum += v[c].x + v[c].y + v[c].z + v[c].w;
        sq  += v[c].x * v[c].x + v[c].y * v[c].y + v[c].z * v[c].z + v[c].w * v[c].w;
    }
#pragma unroll
    for (int o = 16; o > 0; o >>= 1) {
        sum += __shfl_xor_sync(0xffffffffu, sum, o);
        sq  += __shfl_xor_sync(0xffffffffu, sq, o);
    }
    const float mu   = sum * (1.0f / HID);
    const float var  = sq * (1.0f / HID) - mu * mu;
    const float rstd = rsqrtf(var + 1e-5f);

    float4* o4 = reinterpret_cast<float4*>(out + (size_t)row * HID);
    const float4* g4 = reinterpret_cast<const float4*>(gamma);
    const float4* b4 = reinterpret_cast<const float4*>(beta);
#pragma unroll
    for (int c = 0; c < 4; c++) {
        const float4 g  = g4[c * 32 + lane];
        const float4 bt = b4[c * 32 + lane];
        float4 r;
        r.x = (v[c].x - mu) * rstd * g.x + bt.x;
        r.y = (v[c].y - mu) * rstd * g.y + bt.y;
        r.z = (v[c].z - mu) * rstd * g.z + bt.z;
        r.w = (v[c].w - mu) * rstd * g.w + bt.w;
        o4[c * 32 + lane] = r;
    }
}

// ---------------------------------------------------------------------------
extern "C" void kernel_launch(void* const* d_in, const int* in_sizes, int n_in,
                              void* d_out, int out_size)
{
    const float* h_in   = (const float*)d_in[0];
    const float* pos    = (const float*)d_in[1];
    /* d_in[2] = batch (int32) unused: equal-size contiguous molecules */
    const float* centers= (const float*)d_in[3];
    const float* w_rbf  = (const float*)d_in[4];
    const float* b_rbf  = (const float*)d_in[5];
    const float* w_qkv  = (const float*)d_in[6];
    const float* b_qkv  = (const float*)d_in[7];
    const float* w_out  = (const float*)d_in[8];
    const float* b_out  = (const float*)d_in[9];
    const float* gamma  = (const float*)d_in[10];
    const float* beta   = (const float*)d_in[11];
    float* out = (float*)d_out;

    float *qkv, *biasb, *yp;
    __nv_bfloat16 *ahi, *alo, *gghi, *gglo, *wqhi, *wqlo, *wohi, *wolo;
    cudaGetSymbolAddress((void**)&qkv,   g_qkv);
    cudaGetSymbolAddress((void**)&biasb, g_bias);
    cudaGetSymbolAddress((void**)&yp,    g_y);
    cudaGetSymbolAddress((void**)&ahi,   g_ahi);
    cudaGetSymbolAddress((void**)&alo,   g_alo);
    cudaGetSymbolAddress((void**)&gghi,  g_gghi);
    cudaGetSymbolAddress((void**)&gglo,  g_gglo);
    cudaGetSymbolAddress((void**)&wqhi,  g_wqhi);
    cudaGetSymbolAddress((void**)&wqlo,  g_wqlo);
    cudaGetSymbolAddress((void**)&wohi,  g_wohi);
    cudaGetSymbolAddress((void**)&wolo,  g_wolo);

    // Unconditional (idempotent, capture-safe, deterministic — no static guards)
    const int SMEM_SZ = 2 * 65536;  // 128 KB dynamic
    cudaFuncSetAttribute(mmagemm<false>, cudaFuncAttributeMaxDynamicSharedMemorySize, SMEM_SZ);
    cudaFuncSetAttribute(mmagemm<true>,  cudaFuncAttributeMaxDynamicSharedMemorySize, SMEM_SZ);

    // 0) precision-split preprocessing
    split_act<<<2048, 256>>>(h_in, ahi, alo, NPTS * HID / 4);
    transpose_split<<<dim3(HID / 32, QKVW / 32), 256>>>(w_qkv, wqhi, wqlo, HID, QKVW);
    transpose_split<<<dim3(HID / 32, HID / 32), 256>>>(w_out, wohi, wolo, HID, HID);

    // 1) RBF attention bias (independent)
    bias_kernel<<<BSZ, 256>>>(pos, centers, w_rbf, b_rbf, biasb);

    // 2) QKV projection on tensor cores: [65536,512] @ [512,1536]
    mmagemm<false><<<dim3(QKVW / 128, NPTS / 128), 256, SMEM_SZ>>>(
        ahi, alo, wqhi, wqlo, b_qkv, nullptr, qkv, QKVW);

    // 3) Block-diagonal attention (outputs hi/lo split)
    attn_kernel<<<dim3(NH, BSZ), 256>>>(qkv, biasb, gghi, gglo);

    // 4) Out projection + bias + residual on tensor cores
    mmagemm<true><<<dim3(HID / 128, NPTS / 128), 256, SMEM_SZ>>>(
        gghi, gglo, wohi, wolo, b_out, h_in, yp, HID);

    // 5) LayerNorm
    ln_kernel<<<NPTS / 8, 256>>>(yp, gamma, beta, out);
}